// round 2
// baseline (speedup 1.0000x reference)
#include <cuda_runtime.h>

// pre_spikes [8,1,8192] f32, W [8192,8192] f32, thr [8,1,8192] f32,
// const_inp [8,1,8192] f32 -> out [8,1,8192] f32.
#define BB     8
#define MM     8192
#define NN     8192
#define KSPLIT 64
#define K_TILE (MM / KSPLIT)      // 128
#define TPB    256
#define VEC    4
#define NCOLS  (TPB * VEC)        // 1024 columns per block
#define NTILES (NN / NCOLS)       // 8
#define SPIKE_CAP 0.9f

// Deterministic partial-sum scratch: [KSPLIT][B][N] = 16 MB.
__device__ float g_scratch[(size_t)KSPLIT * BB * NN];

// Packed f32x2 FMA (Blackwell): d = a*b + c on both 32-bit halves.
__device__ __forceinline__ void fma2(unsigned long long& d,
                                     unsigned long long a,
                                     unsigned long long b,
                                     unsigned long long c) {
    asm("fma.rn.f32x2 %0, %1, %2, %3;" : "=l"(d) : "l"(a), "l"(b), "l"(c));
}

__global__ __launch_bounds__(TPB)
void snn_gemv_partial(const float* __restrict__ pre,
                      const float* __restrict__ W)
{
    // Pre-spike chunk, each amplitude splatted into both halves of an f32x2:
    // sp2[m][b] = (p, p). 8 KB shared.
    __shared__ unsigned long long sp2[K_TILE][BB];

    const int ks = blockIdx.y;
    const int k0 = ks * K_TILE;
    const int n0 = blockIdx.x * NCOLS + threadIdx.x * VEC;

    // Stage: consecutive threads -> consecutive m (coalesced global read).
    for (int i = threadIdx.x; i < K_TILE * BB; i += TPB) {
        const int b = i / K_TILE;
        const int m = i - b * K_TILE;
        const float p = pre[(size_t)b * MM + k0 + m];
        unsigned long long pk;
        asm("mov.b64 %0, {%1, %1};" : "=l"(pk) : "f"(p));
        sp2[m][b] = pk;
    }
    __syncthreads();

    // 8 batches x 4 columns = 16 f32x2 accumulators.
    unsigned long long acc[BB][2];
#pragma unroll
    for (int b = 0; b < BB; b++) { acc[b][0] = 0ULL; acc[b][1] = 0ULL; }

    const size_t wbase = (size_t)k0 * NN + n0;
    const ulonglong2* __restrict__ wp =
        reinterpret_cast<const ulonglong2*>(W + wbase);
    const size_t wstride = NN / 4;   // ulonglong2 (16B) row stride

#pragma unroll 8
    for (int m = 0; m < K_TILE; m++) {
        const ulonglong2 w = wp[(size_t)m * wstride];   // 4 cols of W (LDG.128)
        const ulonglong2* pv =
            reinterpret_cast<const ulonglong2*>(&sp2[m][0]);
        // 4 LDS.128 fetch the 8 splatted batch amplitudes (broadcast).
        const ulonglong2 p01 = pv[0];
        const ulonglong2 p23 = pv[1];
        const ulonglong2 p45 = pv[2];
        const ulonglong2 p67 = pv[3];
        fma2(acc[0][0], p01.x, w.x, acc[0][0]); fma2(acc[0][1], p01.x, w.y, acc[0][1]);
        fma2(acc[1][0], p01.y, w.x, acc[1][0]); fma2(acc[1][1], p01.y, w.y, acc[1][1]);
        fma2(acc[2][0], p23.x, w.x, acc[2][0]); fma2(acc[2][1], p23.x, w.y, acc[2][1]);
        fma2(acc[3][0], p23.y, w.x, acc[3][0]); fma2(acc[3][1], p23.y, w.y, acc[3][1]);
        fma2(acc[4][0], p45.x, w.x, acc[4][0]); fma2(acc[4][1], p45.x, w.y, acc[4][1]);
        fma2(acc[5][0], p45.y, w.x, acc[5][0]); fma2(acc[5][1], p45.y, w.y, acc[5][1]);
        fma2(acc[6][0], p67.x, w.x, acc[6][0]); fma2(acc[6][1], p67.x, w.y, acc[6][1]);
        fma2(acc[7][0], p67.y, w.x, acc[7][0]); fma2(acc[7][1], p67.y, w.y, acc[7][1]);
    }

    // Each (ks, b, n) slot written exactly once -> no init, no atomics.
    float* base = &g_scratch[(size_t)ks * BB * NN];
#pragma unroll
    for (int b = 0; b < BB; b++) {
        ulonglong2 v; v.x = acc[b][0]; v.y = acc[b][1];
        *reinterpret_cast<ulonglong2*>(base + (size_t)b * NN + n0) = v;
    }
}

#define EPI_TPB 128
__global__ __launch_bounds__(EPI_TPB)
void snn_epilogue(const float* __restrict__ thr,
                  const float* __restrict__ cinp,
                  float* __restrict__ out)
{
    const int i = (blockIdx.x * EPI_TPB + threadIdx.x) * VEC;  // over B*N
    float4 a0 = make_float4(0.f, 0.f, 0.f, 0.f);
    float4 a1 = a0, a2 = a0, a3 = a0;
#pragma unroll 4
    for (int ks = 0; ks < KSPLIT; ks += 4) {
        const float4 v0 = *reinterpret_cast<const float4*>(
            &g_scratch[(size_t)(ks + 0) * BB * NN + i]);
        const float4 v1 = *reinterpret_cast<const float4*>(
            &g_scratch[(size_t)(ks + 1) * BB * NN + i]);
        const float4 v2 = *reinterpret_cast<const float4*>(
            &g_scratch[(size_t)(ks + 2) * BB * NN + i]);
        const float4 v3 = *reinterpret_cast<const float4*>(
            &g_scratch[(size_t)(ks + 3) * BB * NN + i]);
        a0.x += v0.x; a0.y += v0.y; a0.z += v0.z; a0.w += v0.w;
        a1.x += v1.x; a1.y += v1.y; a1.z += v1.z; a1.w += v1.w;
        a2.x += v2.x; a2.y += v2.y; a2.z += v2.z; a2.w += v2.w;
        a3.x += v3.x; a3.y += v3.y; a3.z += v3.z; a3.w += v3.w;
    }
    float4 s = *reinterpret_cast<const float4*>(cinp + i);
    s.x += (a0.x + a1.x) + (a2.x + a3.x);
    s.y += (a0.y + a1.y) + (a2.y + a3.y);
    s.z += (a0.z + a1.z) + (a2.z + a3.z);
    s.w += (a0.w + a1.w) + (a2.w + a3.w);
    const float4 t = *reinterpret_cast<const float4*>(thr + i);
    s.x = fminf(fmaxf(s.x - t.x, 0.f), SPIKE_CAP);
    s.y = fminf(fmaxf(s.y - t.y, 0.f), SPIKE_CAP);
    s.z = fminf(fmaxf(s.z - t.z, 0.f), SPIKE_CAP);
    s.w = fminf(fmaxf(s.w - t.w, 0.f), SPIKE_CAP);
    *reinterpret_cast<float4*>(out + i) = s;
}

extern "C" void kernel_launch(void* const* d_in, const int* in_sizes, int n_in,
                              void* d_out, int out_size)
{
    const float* pre  = (const float*)d_in[0];  // pre_spikes [8,1,8192]
    const float* W    = (const float*)d_in[1];  // W [8192,8192]
    const float* thr  = (const float*)d_in[2];  // thr [8,1,8192]
    const float* cinp = (const float*)d_in[3];  // const_inp [8,1,8192]
    float* out = (float*)d_out;

    dim3 grid(NTILES, KSPLIT);                  // 8 x 64 = 512 blocks
    snn_gemv_partial<<<grid, TPB>>>(pre, W);

    const int n_elems = BB * NN;                // 65536
    snn_epilogue<<<n_elems / (VEC * EPI_TPB), EPI_TPB>>>(thr, cinp, out);
}

// round 3
// speedup vs baseline: 1.2055x; 1.2055x over previous
#include <cuda_runtime.h>

// pre_spikes [8,1,8192] f32, W [8192,8192] f32, thr [8,1,8192] f32,
// const_inp [8,1,8192] f32 -> out [8,1,8192] f32.
#define BB     8
#define MM     8192
#define NN     8192
#define KSPLIT 32
#define K_TILE (MM / KSPLIT)      // 256
#define TPB    128
#define VEC    4
#define NCOLS  (TPB * VEC)        // 512 columns per block
#define NTILES (NN / NCOLS)       // 16
#define SPIKE_CAP 0.9f

typedef unsigned long long ull;

// Deterministic partial-sum scratch: [KSPLIT][B][N] = 8 MB (L2-resident).
__device__ float g_scratch[(size_t)KSPLIT * BB * NN];

// Packed f32x2 FMA (Blackwell): d = a*b + c on both 32-bit halves.
__device__ __forceinline__ void fma2(ull& d, ull a, ull b, ull c) {
    asm("fma.rn.f32x2 %0, %1, %2, %3;" : "=l"(d) : "l"(a), "l"(b), "l"(c));
}

// 16B streaming load (evict-first in L2): W is read exactly once.
__device__ __forceinline__ void ldcs_v2u64(ull& x, ull& y, const void* p) {
    asm("ld.global.cs.v2.u64 {%0, %1}, [%2];" : "=l"(x), "=l"(y) : "l"(p));
}

__global__ __launch_bounds__(TPB)
void snn_gemv_partial(const float* __restrict__ pre,
                      const float* __restrict__ W)
{
    // Pre-spike chunk, each amplitude splatted into both halves of an f32x2:
    // sp2[m][b] = (p, p). 16 KB shared.
    __shared__ ull sp2[K_TILE][BB];

    const int ks = blockIdx.y;
    const int k0 = ks * K_TILE;
    const int n0 = blockIdx.x * NCOLS + threadIdx.x * VEC;

    for (int i = threadIdx.x; i < K_TILE * BB; i += TPB) {
        const int b = i / K_TILE;
        const int m = i - b * K_TILE;
        const float p = pre[(size_t)b * MM + k0 + m];
        ull pk;
        asm("mov.b64 %0, {%1, %1};" : "=l"(pk) : "f"(p));
        sp2[m][b] = pk;
    }
    __syncthreads();

    // 8 batches x 4 columns = 16 f32x2 accumulators.
    ull acc[BB][2];
#pragma unroll
    for (int b = 0; b < BB; b++) { acc[b][0] = 0ULL; acc[b][1] = 0ULL; }

    const char* wbase = reinterpret_cast<const char*>(W + (size_t)k0 * NN + n0);

#pragma unroll 8
    for (int m = 0; m < K_TILE; m++) {
        ull wx, wy;                                   // 4 cols of W (LDG.128, .cs)
        ldcs_v2u64(wx, wy, wbase + (size_t)m * (NN * 4));
        const ulonglong2* pv = reinterpret_cast<const ulonglong2*>(&sp2[m][0]);
        const ulonglong2 p01 = pv[0];                 // broadcast LDS.128
        const ulonglong2 p23 = pv[1];
        const ulonglong2 p45 = pv[2];
        const ulonglong2 p67 = pv[3];
        fma2(acc[0][0], p01.x, wx, acc[0][0]); fma2(acc[0][1], p01.x, wy, acc[0][1]);
        fma2(acc[1][0], p01.y, wx, acc[1][0]); fma2(acc[1][1], p01.y, wy, acc[1][1]);
        fma2(acc[2][0], p23.x, wx, acc[2][0]); fma2(acc[2][1], p23.x, wy, acc[2][1]);
        fma2(acc[3][0], p23.y, wx, acc[3][0]); fma2(acc[3][1], p23.y, wy, acc[3][1]);
        fma2(acc[4][0], p45.x, wx, acc[4][0]); fma2(acc[4][1], p45.x, wy, acc[4][1]);
        fma2(acc[5][0], p45.y, wx, acc[5][0]); fma2(acc[5][1], p45.y, wy, acc[5][1]);
        fma2(acc[6][0], p67.x, wx, acc[6][0]); fma2(acc[6][1], p67.x, wy, acc[6][1]);
        fma2(acc[7][0], p67.y, wx, acc[7][0]); fma2(acc[7][1], p67.y, wy, acc[7][1]);
    }

    // Each (ks, b, n) slot written exactly once -> no init, no atomics.
    float* base = &g_scratch[(size_t)ks * BB * NN];
#pragma unroll
    for (int b = 0; b < BB; b++) {
        ulonglong2 v; v.x = acc[b][0]; v.y = acc[b][1];
        *reinterpret_cast<ulonglong2*>(base + (size_t)b * NN + n0) = v;
    }
}

#define EPI_TPB 128
__global__ __launch_bounds__(EPI_TPB)
void snn_epilogue(const float* __restrict__ thr,
                  const float* __restrict__ cinp,
                  float* __restrict__ out)
{
    // One scalar output element per thread: 65536 threads, 32 independent
    // strided loads each (coalesced within a warp; mostly L2 hits).
    const int i = blockIdx.x * EPI_TPB + threadIdx.x;
    float a0 = 0.f, a1 = 0.f, a2 = 0.f, a3 = 0.f;
#pragma unroll
    for (int ks = 0; ks < KSPLIT; ks += 4) {
        a0 += __ldcs(&g_scratch[(size_t)(ks + 0) * BB * NN + i]);
        a1 += __ldcs(&g_scratch[(size_t)(ks + 1) * BB * NN + i]);
        a2 += __ldcs(&g_scratch[(size_t)(ks + 2) * BB * NN + i]);
        a3 += __ldcs(&g_scratch[(size_t)(ks + 3) * BB * NN + i]);
    }
    const float s = cinp[i] + ((a0 + a1) + (a2 + a3));
    out[i] = fminf(fmaxf(s - thr[i], 0.f), SPIKE_CAP);
}

extern "C" void kernel_launch(void* const* d_in, const int* in_sizes, int n_in,
                              void* d_out, int out_size)
{
    const float* pre  = (const float*)d_in[0];  // pre_spikes [8,1,8192]
    const float* W    = (const float*)d_in[1];  // W [8192,8192]
    const float* thr  = (const float*)d_in[2];  // thr [8,1,8192]
    const float* cinp = (const float*)d_in[3];  // const_inp [8,1,8192]
    float* out = (float*)d_out;

    dim3 grid(NTILES, KSPLIT);                  // 16 x 32 = 512 blocks
    snn_gemv_partial<<<grid, TPB>>>(pre, W);

    const int n_elems = BB * NN;                // 65536
    snn_epilogue<<<n_elems / EPI_TPB, EPI_TPB>>>(thr, cinp, out);
}

// round 4
// speedup vs baseline: 1.2881x; 1.0685x over previous
#include <cuda_runtime.h>

// pre_spikes [8,1,8192] f32, W [8192,8192] f32, thr [8,1,8192] f32,
// const_inp [8,1,8192] f32 -> out [8,1,8192] f32.
#define BB     8
#define MM     8192
#define NN     8192
#define KSPLIT 32
#define K_TILE (MM / KSPLIT)      // 256
#define TPB    64
#define VEC    4
#define NCOLS  (TPB * VEC)        // 256 columns per block
#define NTILES (NN / NCOLS)       // 32
#define SPIKE_CAP 0.9f

typedef unsigned long long ull;

// Deterministic partial-sum scratch: [KSPLIT][B][N] = 8 MB (L2-resident).
__device__ float g_scratch[(size_t)KSPLIT * BB * NN];

// Packed f32x2 FMA (Blackwell): d = a*b + c on both 32-bit halves.
__device__ __forceinline__ void fma2(ull& d, ull a, ull b, ull c) {
    asm("fma.rn.f32x2 %0, %1, %2, %3;" : "=l"(d) : "l"(a), "l"(b), "l"(c));
}

// 16B streaming load (evict-first in L2): W is read exactly once.
__device__ __forceinline__ void ldcs_v2u64(ull& x, ull& y, const void* p) {
    asm("ld.global.cs.v2.u64 {%0, %1}, [%2];" : "=l"(x), "=l"(y) : "l"(p));
}

__global__ __launch_bounds__(TPB)
void snn_gemv_partial(const float* __restrict__ pre,
                      const float* __restrict__ W)
{
    // Pre-spike chunk, each amplitude splatted into both halves of an f32x2:
    // sp2[m][b] = (p, p). 16 KB shared.
    __shared__ ull sp2[K_TILE][BB];

    const int ks = blockIdx.y;
    const int k0 = ks * K_TILE;
    const int n0 = blockIdx.x * NCOLS + threadIdx.x * VEC;

    for (int i = threadIdx.x; i < K_TILE * BB; i += TPB) {
        const int b = i >> 8;           // i / K_TILE (K_TILE = 256)
        const int m = i & (K_TILE - 1);
        const float p = pre[(size_t)b * MM + k0 + m];
        ull pk;
        asm("mov.b64 %0, {%1, %1};" : "=l"(pk) : "f"(p));
        sp2[m][b] = pk;
    }
    __syncthreads();

    // 8 batches x 4 columns = 16 f32x2 accumulators.
    ull acc[BB][2];
#pragma unroll
    for (int b = 0; b < BB; b++) { acc[b][0] = 0ULL; acc[b][1] = 0ULL; }

    const char* wbase = reinterpret_cast<const char*>(W + (size_t)k0 * NN + n0);

#pragma unroll 8
    for (int m = 0; m < K_TILE; m++) {
        ull wx, wy;                                   // 4 cols of W (LDG.128, .cs)
        ldcs_v2u64(wx, wy, wbase + (size_t)m * (NN * 4));
        const ulonglong2* pv = reinterpret_cast<const ulonglong2*>(&sp2[m][0]);
        const ulonglong2 p01 = pv[0];                 // broadcast LDS.128
        const ulonglong2 p23 = pv[1];
        const ulonglong2 p45 = pv[2];
        const ulonglong2 p67 = pv[3];
        fma2(acc[0][0], p01.x, wx, acc[0][0]); fma2(acc[0][1], p01.x, wy, acc[0][1]);
        fma2(acc[1][0], p01.y, wx, acc[1][0]); fma2(acc[1][1], p01.y, wy, acc[1][1]);
        fma2(acc[2][0], p23.x, wx, acc[2][0]); fma2(acc[2][1], p23.x, wy, acc[2][1]);
        fma2(acc[3][0], p23.y, wx, acc[3][0]); fma2(acc[3][1], p23.y, wy, acc[3][1]);
        fma2(acc[4][0], p45.x, wx, acc[4][0]); fma2(acc[4][1], p45.x, wy, acc[4][1]);
        fma2(acc[5][0], p45.y, wx, acc[5][0]); fma2(acc[5][1], p45.y, wy, acc[5][1]);
        fma2(acc[6][0], p67.x, wx, acc[6][0]); fma2(acc[6][1], p67.x, wy, acc[6][1]);
        fma2(acc[7][0], p67.y, wx, acc[7][0]); fma2(acc[7][1], p67.y, wy, acc[7][1]);
    }

    // Each (ks, b, n) slot written exactly once -> no init, no atomics.
    float* base = &g_scratch[(size_t)ks * BB * NN];
#pragma unroll
    for (int b = 0; b < BB; b++) {
        ulonglong2 v; v.x = acc[b][0]; v.y = acc[b][1];
        *reinterpret_cast<ulonglong2*>(base + (size_t)b * NN + n0) = v;
    }
}

#define EPI_TPB 64
__global__ __launch_bounds__(EPI_TPB)
void snn_epilogue(const float* __restrict__ thr,
                  const float* __restrict__ cinp,
                  float* __restrict__ out)
{
    // One scalar output element per thread; 32 fully independent loads
    // (8 accumulators, full unroll) against L2-resident scratch.
    const int i = blockIdx.x * EPI_TPB + threadIdx.x;
    float a0 = 0.f, a1 = 0.f, a2 = 0.f, a3 = 0.f;
    float a4 = 0.f, a5 = 0.f, a6 = 0.f, a7 = 0.f;
#pragma unroll
    for (int ks = 0; ks < KSPLIT; ks += 8) {
        a0 += __ldcs(&g_scratch[(size_t)(ks + 0) * BB * NN + i]);
        a1 += __ldcs(&g_scratch[(size_t)(ks + 1) * BB * NN + i]);
        a2 += __ldcs(&g_scratch[(size_t)(ks + 2) * BB * NN + i]);
        a3 += __ldcs(&g_scratch[(size_t)(ks + 3) * BB * NN + i]);
        a4 += __ldcs(&g_scratch[(size_t)(ks + 4) * BB * NN + i]);
        a5 += __ldcs(&g_scratch[(size_t)(ks + 5) * BB * NN + i]);
        a6 += __ldcs(&g_scratch[(size_t)(ks + 6) * BB * NN + i]);
        a7 += __ldcs(&g_scratch[(size_t)(ks + 7) * BB * NN + i]);
    }
    const float s = cinp[i] + (((a0 + a1) + (a2 + a3)) + ((a4 + a5) + (a6 + a7)));
    out[i] = fminf(fmaxf(s - thr[i], 0.f), SPIKE_CAP);
}

extern "C" void kernel_launch(void* const* d_in, const int* in_sizes, int n_in,
                              void* d_out, int out_size)
{
    const float* pre  = (const float*)d_in[0];  // pre_spikes [8,1,8192]
    const float* W    = (const float*)d_in[1];  // W [8192,8192]
    const float* thr  = (const float*)d_in[2];  // thr [8,1,8192]
    const float* cinp = (const float*)d_in[3];  // const_inp [8,1,8192]
    float* out = (float*)d_out;

    dim3 grid(NTILES, KSPLIT);                  // 32 x 32 = 1024 blocks
    snn_gemv_partial<<<grid, TPB>>>(pre, W);

    const int n_elems = BB * NN;                // 65536
    snn_epilogue<<<n_elems / EPI_TPB, EPI_TPB>>>(thr, cinp, out);
}

// round 5
// speedup vs baseline: 1.3356x; 1.0368x over previous
#include <cuda_runtime.h>

// pre_spikes [8,1,8192] f32, W [8192,8192] f32, thr [8,1,8192] f32,
// const_inp [8,1,8192] f32 -> out [8,1,8192] f32.
#define BB     8
#define MM     8192
#define NN     8192
#define KSPLIT 32
#define K_TILE (MM / KSPLIT)      // 256
#define TPB    64
#define VEC    4
#define NCOLS  (TPB * VEC)        // 256 columns per block
#define NTILES (NN / NCOLS)       // 32
#define PREF   16                 // W rows prefetched into registers per stage
#define SPIKE_CAP 0.9f

typedef unsigned long long ull;

// Deterministic partial-sum scratch: [KSPLIT][B][N] = 8 MB.
__device__ float g_scratch[(size_t)KSPLIT * BB * NN];

// Packed f32x2 FMA (Blackwell): d = a*b + c on both 32-bit halves.
__device__ __forceinline__ void fma2(ull& d, ull a, ull b, ull c) {
    asm("fma.rn.f32x2 %0, %1, %2, %3;" : "=l"(d) : "l"(a), "l"(b), "l"(c));
}

// 16B streaming load (evict-first in L2): W is read exactly once.
__device__ __forceinline__ void ldcs_v2u64(ull& x, ull& y, const void* p) {
    asm("ld.global.cs.v2.u64 {%0, %1}, [%2];" : "=l"(x), "=l"(y) : "l"(p));
}

__global__ __launch_bounds__(TPB)
void snn_gemv_partial(const float* __restrict__ pre,
                      const float* __restrict__ W)
{
    // Pre-spike chunk, each amplitude splatted into both halves of an f32x2:
    // sp2[m][b] = (p, p). 16 KB shared.
    __shared__ ull sp2[K_TILE][BB];

    const int ks = blockIdx.y;
    const int k0 = ks * K_TILE;
    const int n0 = blockIdx.x * NCOLS + threadIdx.x * VEC;

    for (int i = threadIdx.x; i < K_TILE * BB; i += TPB) {
        const int b = i >> 8;           // i / K_TILE (K_TILE = 256)
        const int m = i & (K_TILE - 1);
        const float p = pre[(size_t)b * MM + k0 + m];
        ull pk;
        asm("mov.b64 %0, {%1, %1};" : "=l"(pk) : "f"(p));
        sp2[m][b] = pk;
    }
    __syncthreads();

    // 8 batches x 4 columns = 16 f32x2 accumulators.
    ull acc[BB][2];
#pragma unroll
    for (int b = 0; b < BB; b++) { acc[b][0] = 0ULL; acc[b][1] = 0ULL; }

    const char* wbase = reinterpret_cast<const char*>(W + (size_t)k0 * NN + n0);

    // Two-phase inner loop: front-batch PREF independent LDG.128 into a
    // register buffer (MLP_p1 = 16), then consume with LDS + FFMA2.
    for (int mb = 0; mb < K_TILE; mb += PREF) {
        ull wx[PREF], wy[PREF];
#pragma unroll
        for (int j = 0; j < PREF; j++) {
            ldcs_v2u64(wx[j], wy[j],
                       wbase + (size_t)(mb + j) * (NN * 4));
        }
#pragma unroll
        for (int j = 0; j < PREF; j++) {
            const ulonglong2* pv =
                reinterpret_cast<const ulonglong2*>(&sp2[mb + j][0]);
            const ulonglong2 p01 = pv[0];             // broadcast LDS.128
            const ulonglong2 p23 = pv[1];
            const ulonglong2 p45 = pv[2];
            const ulonglong2 p67 = pv[3];
            const ull xw = wx[j], yw = wy[j];
            fma2(acc[0][0], p01.x, xw, acc[0][0]); fma2(acc[0][1], p01.x, yw, acc[0][1]);
            fma2(acc[1][0], p01.y, xw, acc[1][0]); fma2(acc[1][1], p01.y, yw, acc[1][1]);
            fma2(acc[2][0], p23.x, xw, acc[2][0]); fma2(acc[2][1], p23.x, yw, acc[2][1]);
            fma2(acc[3][0], p23.y, xw, acc[3][0]); fma2(acc[3][1], p23.y, yw, acc[3][1]);
            fma2(acc[4][0], p45.x, xw, acc[4][0]); fma2(acc[4][1], p45.x, yw, acc[4][1]);
            fma2(acc[5][0], p45.y, xw, acc[5][0]); fma2(acc[5][1], p45.y, yw, acc[5][1]);
            fma2(acc[6][0], p67.x, xw, acc[6][0]); fma2(acc[6][1], p67.x, yw, acc[6][1]);
            fma2(acc[7][0], p67.y, xw, acc[7][0]); fma2(acc[7][1], p67.y, yw, acc[7][1]);
        }
    }

    // Each (ks, b, n) slot written exactly once -> no init, no atomics.
    float* base = &g_scratch[(size_t)ks * BB * NN];
#pragma unroll
    for (int b = 0; b < BB; b++) {
        ulonglong2 v; v.x = acc[b][0]; v.y = acc[b][1];
        *reinterpret_cast<ulonglong2*>(base + (size_t)b * NN + n0) = v;
    }
}

#define EPI_TPB 64
__global__ __launch_bounds__(EPI_TPB)
void snn_epilogue(const float* __restrict__ thr,
                  const float* __restrict__ cinp,
                  float* __restrict__ out)
{
    // One scalar output element per thread; 32 fully independent loads.
    const int i = blockIdx.x * EPI_TPB + threadIdx.x;
    float a0 = 0.f, a1 = 0.f, a2 = 0.f, a3 = 0.f;
    float a4 = 0.f, a5 = 0.f, a6 = 0.f, a7 = 0.f;
#pragma unroll
    for (int ks = 0; ks < KSPLIT; ks += 8) {
        a0 += __ldcs(&g_scratch[(size_t)(ks + 0) * BB * NN + i]);
        a1 += __ldcs(&g_scratch[(size_t)(ks + 1) * BB * NN + i]);
        a2 += __ldcs(&g_scratch[(size_t)(ks + 2) * BB * NN + i]);
        a3 += __ldcs(&g_scratch[(size_t)(ks + 3) * BB * NN + i]);
        a4 += __ldcs(&g_scratch[(size_t)(ks + 4) * BB * NN + i]);
        a5 += __ldcs(&g_scratch[(size_t)(ks + 5) * BB * NN + i]);
        a6 += __ldcs(&g_scratch[(size_t)(ks + 6) * BB * NN + i]);
        a7 += __ldcs(&g_scratch[(size_t)(ks + 7) * BB * NN + i]);
    }
    const float s = cinp[i] + (((a0 + a1) + (a2 + a3)) + ((a4 + a5) + (a6 + a7)));
    out[i] = fminf(fmaxf(s - thr[i], 0.f), SPIKE_CAP);
}

extern "C" void kernel_launch(void* const* d_in, const int* in_sizes, int n_in,
                              void* d_out, int out_size)
{
    const float* pre  = (const float*)d_in[0];  // pre_spikes [8,1,8192]
    const float* W    = (const float*)d_in[1];  // W [8192,8192]
    const float* thr  = (const float*)d_in[2];  // thr [8,1,8192]
    const float* cinp = (const float*)d_in[3];  // const_inp [8,1,8192]
    float* out = (float*)d_out;

    dim3 grid(NTILES, KSPLIT);                  // 32 x 32 = 1024 blocks
    snn_gemv_partial<<<grid, TPB>>>(pre, W);

    const int n_elems = BB * NN;                // 65536
    snn_epilogue<<<n_elems / EPI_TPB, EPI_TPB>>>(thr, cinp, out);
}

// round 6
// speedup vs baseline: 1.3755x; 1.0299x over previous
#include <cuda_runtime.h>

// pre_spikes [8,1,8192] f32, W [8192,8192] f32, thr [8,1,8192] f32,
// const_inp [8,1,8192] f32 -> out [8,1,8192] f32.
#define BB     8
#define MM     8192
#define NN     8192
#define KSPLIT 32
#define K_TILE (MM / KSPLIT)      // 256
#define TPB    64
#define VEC    4
#define NCOLS  (TPB * VEC)        // 256 columns per block
#define NTILES (NN / NCOLS)       // 32
#define PREF   16                 // W rows prefetched into registers per stage
#define SPIKE_CAP 0.9f

typedef unsigned long long ull;

// L2-resident accumulator [B][N] = 256 KB. Zero at module load; the epilogue
// resets it to zero every call, so every kernel_launch sees zeros.
__device__ float g_accum[(size_t)BB * NN];

// Packed f32x2 FMA (Blackwell): d = a*b + c on both 32-bit halves.
__device__ __forceinline__ void fma2(ull& d, ull a, ull b, ull c) {
    asm("fma.rn.f32x2 %0, %1, %2, %3;" : "=l"(d) : "l"(a), "l"(b), "l"(c));
}

// 16B streaming load (evict-first in L2): W is read exactly once.
__device__ __forceinline__ void ldcs_v2u64(ull& x, ull& y, const void* p) {
    asm("ld.global.cs.v2.u64 {%0, %1}, [%2];" : "=l"(x), "=l"(y) : "l"(p));
}

// 16B vector reduction into global (sm_90+): one L2 atomic op per 4 floats.
__device__ __forceinline__ void redg_v4f32(float* p, ull lo, ull hi) {
    const float2 a = *reinterpret_cast<const float2*>(&lo);
    const float2 b = *reinterpret_cast<const float2*>(&hi);
    asm volatile("red.global.add.v4.f32 [%0], {%1, %2, %3, %4};"
                 :: "l"(p), "f"(a.x), "f"(a.y), "f"(b.x), "f"(b.y)
                 : "memory");
}

__global__ __launch_bounds__(TPB)
void snn_gemv_partial(const float* __restrict__ pre,
                      const float* __restrict__ W)
{
    // Pre-spike chunk, each amplitude splatted into both halves of an f32x2.
    __shared__ ull sp2[K_TILE][BB];

    const int ks = blockIdx.y;
    const int k0 = ks * K_TILE;
    const int n0 = blockIdx.x * NCOLS + threadIdx.x * VEC;

    for (int i = threadIdx.x; i < K_TILE * BB; i += TPB) {
        const int b = i >> 8;           // i / K_TILE (K_TILE = 256)
        const int m = i & (K_TILE - 1);
        const float p = pre[(size_t)b * MM + k0 + m];
        ull pk;
        asm("mov.b64 %0, {%1, %1};" : "=l"(pk) : "f"(p));
        sp2[m][b] = pk;
    }
    __syncthreads();

    // 8 batches x 4 columns = 16 f32x2 accumulators.
    ull acc[BB][2];
#pragma unroll
    for (int b = 0; b < BB; b++) { acc[b][0] = 0ULL; acc[b][1] = 0ULL; }

    const char* wbase = reinterpret_cast<const char*>(W + (size_t)k0 * NN + n0);

    // Two-phase inner loop: front-batch PREF independent LDG.128 (MLP_p1=16),
    // then consume with broadcast LDS + FFMA2.
    for (int mb = 0; mb < K_TILE; mb += PREF) {
        ull wx[PREF], wy[PREF];
#pragma unroll
        for (int j = 0; j < PREF; j++) {
            ldcs_v2u64(wx[j], wy[j],
                       wbase + (size_t)(mb + j) * (NN * 4));
        }
#pragma unroll
        for (int j = 0; j < PREF; j++) {
            const ulonglong2* pv =
                reinterpret_cast<const ulonglong2*>(&sp2[mb + j][0]);
            const ulonglong2 p01 = pv[0];
            const ulonglong2 p23 = pv[1];
            const ulonglong2 p45 = pv[2];
            const ulonglong2 p67 = pv[3];
            const ull xw = wx[j], yw = wy[j];
            fma2(acc[0][0], p01.x, xw, acc[0][0]); fma2(acc[0][1], p01.x, yw, acc[0][1]);
            fma2(acc[1][0], p01.y, xw, acc[1][0]); fma2(acc[1][1], p01.y, yw, acc[1][1]);
            fma2(acc[2][0], p23.x, xw, acc[2][0]); fma2(acc[2][1], p23.x, yw, acc[2][1]);
            fma2(acc[3][0], p23.y, xw, acc[3][0]); fma2(acc[3][1], p23.y, yw, acc[3][1]);
            fma2(acc[4][0], p45.x, xw, acc[4][0]); fma2(acc[4][1], p45.x, yw, acc[4][1]);
            fma2(acc[5][0], p45.y, xw, acc[5][0]); fma2(acc[5][1], p45.y, yw, acc[5][1]);
            fma2(acc[6][0], p67.x, xw, acc[6][0]); fma2(acc[6][1], p67.x, yw, acc[6][1]);
            fma2(acc[7][0], p67.y, xw, acc[7][0]); fma2(acc[7][1], p67.y, yw, acc[7][1]);
        }
    }

    // Accumulate partials straight into the L2-resident accumulator:
    // 8 vector REDs per thread, no scratch, no extra DRAM round trip.
#pragma unroll
    for (int b = 0; b < BB; b++) {
        redg_v4f32(&g_accum[(size_t)b * NN + n0], acc[b][0], acc[b][1]);
    }
}

#define EPI_TPB 128
__global__ __launch_bounds__(EPI_TPB)
void snn_epilogue(const float* __restrict__ thr,
                  const float* __restrict__ cinp,
                  float* __restrict__ out)
{
    // accum values were just written via L2 atomics -> L2 hits.
    const int i = blockIdx.x * EPI_TPB + threadIdx.x;   // over B*N
    const float s = g_accum[i] + cinp[i];
    g_accum[i] = 0.f;   // restore the zero invariant for the next replay
    out[i] = fminf(fmaxf(s - thr[i], 0.f), SPIKE_CAP);
}

extern "C" void kernel_launch(void* const* d_in, const int* in_sizes, int n_in,
                              void* d_out, int out_size)
{
    const float* pre  = (const float*)d_in[0];  // pre_spikes [8,1,8192]
    const float* W    = (const float*)d_in[1];  // W [8192,8192]
    const float* thr  = (const float*)d_in[2];  // thr [8,1,8192]
    const float* cinp = (const float*)d_in[3];  // const_inp [8,1,8192]
    float* out = (float*)d_out;

    dim3 grid(NTILES, KSPLIT);                  // 32 x 32 = 1024 blocks
    snn_gemv_partial<<<grid, TPB>>>(pre, W);

    const int n_elems = BB * NN;                // 65536
    snn_epilogue<<<n_elems / EPI_TPB, EPI_TPB>>>(thr, cinp, out);
}

// round 7
// speedup vs baseline: 1.4187x; 1.0314x over previous
#include <cuda_runtime.h>

// pre_spikes [8,1,8192] f32, W [8192,8192] f32, thr [8,1,8192] f32,
// const_inp [8,1,8192] f32 -> out [8,1,8192] f32.
#define BB     8
#define MM     8192
#define NN     8192
#define KSPLIT 64
#define K_TILE (MM / KSPLIT)      // 128
#define TPB    64
#define VEC    4
#define NCOLS  (TPB * VEC)        // 256 columns per block
#define NTILES (NN / NCOLS)       // 32
#define PREF   16                 // W rows prefetched into registers per stage
#define SPIKE_CAP 0.9f

typedef unsigned long long ull;

// L2-resident accumulator [B][N] = 256 KB. Zero at load; the finishing block
// of each N-tile re-zeroes its slice every call (graph-replay invariant).
__device__ float g_accum[(size_t)BB * NN];
// Per-N-tile arrival counters (reset by the finishing block).
__device__ unsigned int g_count[NTILES];

// Packed f32x2 FMA (Blackwell): d = a*b + c on both 32-bit halves.
__device__ __forceinline__ void fma2(ull& d, ull a, ull b, ull c) {
    asm("fma.rn.f32x2 %0, %1, %2, %3;" : "=l"(d) : "l"(a), "l"(b), "l"(c));
}

// 16B streaming load (evict-first in L2): W is read exactly once.
__device__ __forceinline__ void ldcs_v2u64(ull& x, ull& y, const void* p) {
    asm("ld.global.cs.v2.u64 {%0, %1}, [%2];" : "=l"(x), "=l"(y) : "l"(p));
}

// 16B vector reduction into global (sm_90+): one L2 atomic op per 4 floats.
__device__ __forceinline__ void redg_v4f32(float* p, ull lo, ull hi) {
    const float2 a = *reinterpret_cast<const float2*>(&lo);
    const float2 b = *reinterpret_cast<const float2*>(&hi);
    asm volatile("red.global.add.v4.f32 [%0], {%1, %2, %3, %4};"
                 :: "l"(p), "f"(a.x), "f"(a.y), "f"(b.x), "f"(b.y)
                 : "memory");
}

__global__ __launch_bounds__(TPB)
void snn_fused(const float* __restrict__ pre,
               const float* __restrict__ W,
               const float* __restrict__ thr,
               const float* __restrict__ cinp,
               float* __restrict__ out)
{
    // Pre-spike chunk, each amplitude splatted into both halves of an f32x2.
    __shared__ ull sp2[K_TILE][BB];
    __shared__ bool s_last;

    const int ks = blockIdx.y;
    const int k0 = ks * K_TILE;
    const int tile = blockIdx.x;
    const int n0 = tile * NCOLS + threadIdx.x * VEC;

    for (int i = threadIdx.x; i < K_TILE * BB; i += TPB) {
        const int b = i >> 7;           // i / K_TILE (K_TILE = 128)
        const int m = i & (K_TILE - 1);
        const float p = pre[(size_t)b * MM + k0 + m];
        ull pk;
        asm("mov.b64 %0, {%1, %1};" : "=l"(pk) : "f"(p));
        sp2[m][b] = pk;
    }
    __syncthreads();

    // 8 batches x 4 columns = 16 f32x2 accumulators.
    ull acc[BB][2];
#pragma unroll
    for (int b = 0; b < BB; b++) { acc[b][0] = 0ULL; acc[b][1] = 0ULL; }

    const char* wbase = reinterpret_cast<const char*>(W + (size_t)k0 * NN + n0);

    // Two-phase inner loop: front-batch PREF independent LDG.128 (MLP=16),
    // then consume with broadcast LDS + FFMA2.
    for (int mb = 0; mb < K_TILE; mb += PREF) {
        ull wx[PREF], wy[PREF];
#pragma unroll
        for (int j = 0; j < PREF; j++) {
            ldcs_v2u64(wx[j], wy[j],
                       wbase + (size_t)(mb + j) * (NN * 4));
        }
#pragma unroll
        for (int j = 0; j < PREF; j++) {
            const ulonglong2* pv =
                reinterpret_cast<const ulonglong2*>(&sp2[mb + j][0]);
            const ulonglong2 p01 = pv[0];
            const ulonglong2 p23 = pv[1];
            const ulonglong2 p45 = pv[2];
            const ulonglong2 p67 = pv[3];
            const ull xw = wx[j], yw = wy[j];
            fma2(acc[0][0], p01.x, xw, acc[0][0]); fma2(acc[0][1], p01.x, yw, acc[0][1]);
            fma2(acc[1][0], p01.y, xw, acc[1][0]); fma2(acc[1][1], p01.y, yw, acc[1][1]);
            fma2(acc[2][0], p23.x, xw, acc[2][0]); fma2(acc[2][1], p23.x, yw, acc[2][1]);
            fma2(acc[3][0], p23.y, xw, acc[3][0]); fma2(acc[3][1], p23.y, yw, acc[3][1]);
            fma2(acc[4][0], p45.x, xw, acc[4][0]); fma2(acc[4][1], p45.x, yw, acc[4][1]);
            fma2(acc[5][0], p45.y, xw, acc[5][0]); fma2(acc[5][1], p45.y, yw, acc[5][1]);
            fma2(acc[6][0], p67.x, xw, acc[6][0]); fma2(acc[6][1], p67.x, yw, acc[6][1]);
            fma2(acc[7][0], p67.y, xw, acc[7][0]); fma2(acc[7][1], p67.y, yw, acc[7][1]);
        }
    }

    // Accumulate partials into the L2-resident accumulator.
#pragma unroll
    for (int b = 0; b < BB; b++) {
        redg_v4f32(&g_accum[(size_t)b * NN + n0], acc[b][0], acc[b][1]);
    }

    // ---- Arrival protocol (threadfence-reduction pattern) ----
    __threadfence();            // make this thread's REDs globally visible
    __syncthreads();            // all threads' REDs+fences precede the bump
    if (threadIdx.x == 0) {
        const unsigned int prev = atomicAdd(&g_count[tile], 1u);
        s_last = (prev == KSPLIT - 1);
    }
    __syncthreads();
    if (!s_last) return;

    // ---- Last block of this N-tile: epilogue for 8 batches x 256 columns ----
    __threadfence();            // acquire: see all other blocks' REDs

    const int nb = tile * NCOLS;
    // 2048 elements = 512 float4; 8 float4 per thread.
#pragma unroll
    for (int v = 0; v < 8; v++) {
        const int e = (v * TPB + threadIdx.x) * VEC;   // 0..2047, vec-aligned
        const int b = e >> 8;                          // e / NCOLS
        const int n = nb + (e & (NCOLS - 1));
        const size_t idx = (size_t)b * NN + n;

        float4 s = *reinterpret_cast<const float4*>(&g_accum[idx]);
        const float4 c = *reinterpret_cast<const float4*>(&cinp[idx]);
        const float4 t = *reinterpret_cast<const float4*>(&thr[idx]);
        s.x = fminf(fmaxf(s.x + c.x - t.x, 0.f), SPIKE_CAP);
        s.y = fminf(fmaxf(s.y + c.y - t.y, 0.f), SPIKE_CAP);
        s.z = fminf(fmaxf(s.z + c.z - t.z, 0.f), SPIKE_CAP);
        s.w = fminf(fmaxf(s.w + c.w - t.w, 0.f), SPIKE_CAP);
        *reinterpret_cast<float4*>(&out[idx]) = s;

        // Restore the zero invariant for the next graph replay.
        *reinterpret_cast<float4*>(&g_accum[idx]) =
            make_float4(0.f, 0.f, 0.f, 0.f);
    }
    if (threadIdx.x == 0) g_count[tile] = 0u;   // reset counter for next call
}

extern "C" void kernel_launch(void* const* d_in, const int* in_sizes, int n_in,
                              void* d_out, int out_size)
{
    const float* pre  = (const float*)d_in[0];  // pre_spikes [8,1,8192]
    const float* W    = (const float*)d_in[1];  // W [8192,8192]
    const float* thr  = (const float*)d_in[2];  // thr [8,1,8192]
    const float* cinp = (const float*)d_in[3];  // const_inp [8,1,8192]
    float* out = (float*)d_out;

    dim3 grid(NTILES, KSPLIT);                  // 32 x 64 = 2048 blocks (~2 waves)
    snn_fused<<<grid, TPB>>>(pre, W, thr, cinp, out);
}